// round 1
// baseline (speedup 1.0000x reference)
#include <cuda_runtime.h>
#include <cstdint>

// Problem constants
#define E_ 8
#define T_ 2048
#define H_ 2048
#define D_ 4096
#define R_ 8
#define SCALE_ 2.0f

// Scratch (allocation-free rule: __device__ globals)
__device__ float g_h[(size_t)E_ * T_ * D_];        // 256 MB intermediate h
__device__ float g_low_gu[E_ * T_ * R_];
__device__ float g_low_d[E_ * T_ * R_];

// ---------------------------------------------------------------------------
// PTX helpers
// ---------------------------------------------------------------------------
__device__ __forceinline__ uint32_t smem_u32(const void* p) {
    return (uint32_t)__cvta_generic_to_shared(p);
}
__device__ __forceinline__ void cp_async16(uint32_t dst, const void* src) {
    asm volatile("cp.async.cg.shared.global [%0], [%1], 16;\n" :: "r"(dst), "l"(src));
}
__device__ __forceinline__ void cp_commit() {
    asm volatile("cp.async.commit_group;\n");
}
template <int N>
__device__ __forceinline__ void cp_wait() {
    asm volatile("cp.async.wait_group %0;\n" :: "n"(N));
}
__device__ __forceinline__ void ldsm4(uint32_t addr, uint32_t& r0, uint32_t& r1,
                                      uint32_t& r2, uint32_t& r3) {
    asm volatile("ldmatrix.sync.aligned.m8n8.x4.shared.b16 {%0,%1,%2,%3}, [%4];\n"
                 : "=r"(r0), "=r"(r1), "=r"(r2), "=r"(r3) : "r"(addr));
}
// fp32 -> tf32 with round-to-nearest (RNA). Bias-free: essential for 1e-3 accuracy.
__device__ __forceinline__ uint32_t cvt_tf32(uint32_t bits) {
    uint32_t d;
    asm("cvt.rna.tf32.f32 %0, %1;\n" : "=r"(d) : "f"(__uint_as_float(bits)));
    return d;
}
__device__ __forceinline__ void mma_tf32(float* c, const uint32_t* a, const uint32_t* b) {
    asm volatile(
        "mma.sync.aligned.m16n8k8.row.col.f32.tf32.tf32.f32 "
        "{%0,%1,%2,%3}, {%4,%5,%6,%7}, {%8,%9}, {%0,%1,%2,%3};\n"
        : "+f"(c[0]), "+f"(c[1]), "+f"(c[2]), "+f"(c[3])
        : "r"(a[0]), "r"(a[1]), "r"(a[2]), "r"(a[3]), "r"(b[0]), "r"(b[1]));
}

// ---------------------------------------------------------------------------
// Rank-8 projection: LOW[e,t,r] = sum_k X[e,t,k] * A[e,r,k]   (fp32, exact)
// WHICH==0: X = hidden_states (K=H) -> g_low_gu; WHICH==1: X = g_h (K=D) -> g_low_d
// ---------------------------------------------------------------------------
template <int WHICH>
__global__ void __launch_bounds__(256) lora_low_kernel(const float* __restrict__ xin,
                                                       const float* __restrict__ Ain) {
    constexpr int K = (WHICH == 0) ? H_ : D_;
    constexpr int K4 = K / 4;
    const float* X = (WHICH == 0) ? xin : g_h;
    float* LOWOUT = (WHICH == 0) ? g_low_gu : g_low_d;

    const int e = blockIdx.y;
    const int wid = threadIdx.x >> 5;
    const int lane = threadIdx.x & 31;
    const int t = blockIdx.x * 8 + wid;

    const float4* x4 = (const float4*)(X + ((size_t)e * T_ + t) * K);
    const float4* a4 = (const float4*)(Ain + (size_t)e * R_ * K);

    float acc[R_];
#pragma unroll
    for (int r = 0; r < R_; r++) acc[r] = 0.0f;

    for (int k = lane; k < K4; k += 32) {
        float4 xv = x4[k];
#pragma unroll
        for (int r = 0; r < R_; r++) {
            float4 av = a4[(size_t)r * K4 + k];
            acc[r] += xv.x * av.x + xv.y * av.y + xv.z * av.z + xv.w * av.w;
        }
    }
#pragma unroll
    for (int r = 0; r < R_; r++) {
#pragma unroll
        for (int off = 16; off > 0; off >>= 1)
            acc[r] += __shfl_xor_sync(0xffffffffu, acc[r], off);
    }
    if (lane == 0) {
        float* dst = LOWOUT + ((size_t)e * T_ + t) * R_;
#pragma unroll
        for (int r = 0; r < R_; r++) dst[r] = acc[r];
    }
}

// ---------------------------------------------------------------------------
// Tiled TF32 tensor-core GEMM with LoRA epilogue.
// PHASE==1: fused gate/up GEMM + SiLU-mul -> g_h    (K=H, N=D, NB=2 B-tiles)
// PHASE==2: down GEMM -> out                        (K=D, N=H, NB=1)
// CTA tile 128x128, BK=32, 8 warps (2x4), warp tile 64x32, cp.async pipeline.
// Smem XOR swizzle: 16B granule gc stored at gc ^ (row&7) -> conflict-free ldmatrix.
// ---------------------------------------------------------------------------
template <int PHASE>
__global__ void __launch_bounds__(256, (PHASE == 1) ? 1 : 2) gemm_tc_kernel(
    const float* __restrict__ xin, const float* __restrict__ W,
    const float* __restrict__ BL, float* __restrict__ outp) {
    constexpr int KD = (PHASE == 1) ? H_ : D_;
    constexpr int OUTS = (PHASE == 1) ? D_ : H_;
    constexpr int NB = (PHASE == 1) ? 2 : 1;
    constexpr int KT = KD / 32;
    constexpr int STAGES = 3;
    constexpr int WAITN = STAGES - 2;
    constexpr int STAGE_FL = 4096 * (1 + NB);

    extern __shared__ float smem[];

    const float* Ain = (PHASE == 1) ? xin : g_h;
    const float* LOW = (PHASE == 1) ? g_low_gu : g_low_d;
    float* OUT = (PHASE == 1) ? g_h : outp;

    const int e = blockIdx.z;
    const int m0 = blockIdx.x * 128;
    const int n0 = blockIdx.y * 128;

    const int tid = threadIdx.x;
    const int lane = tid & 31;
    const int wid = tid >> 5;
    const int wm = wid & 1;
    const int wn = wid >> 1;

    const float* Abase = Ain + ((size_t)e * T_ + m0) * KD;
    const float* Wb0 = W + ((size_t)e * NB * OUTS + n0) * KD;            // gate / down rows
    const float* Wb1 = W + ((size_t)e * NB * OUTS + OUTS + n0) * KD;     // up rows (NB==2)

    const uint32_t sbase = smem_u32(smem);

    auto load_stage = [&](int s, int k0) {
        const uint32_t st = sbase + (uint32_t)s * (uint32_t)(STAGE_FL * 4);
#pragma unroll
        for (int i = 0; i < 4; i++) {
            int gi = tid + i * 256;          // 1024 granules (128 rows x 8)
            int row = gi >> 3;
            int gc = gi & 7;
            uint32_t soff = (uint32_t)((row << 5) + ((gc ^ (row & 7)) << 2)) << 2;
            size_t goff = (size_t)row * KD + (k0 + (gc << 2));
            cp_async16(st + soff, Abase + goff);
            cp_async16(st + 16384u + soff, Wb0 + goff);
            if constexpr (NB == 2) cp_async16(st + 32768u + soff, Wb1 + goff);
        }
    };

    float acc[NB][4][4][4];
#pragma unroll
    for (int b = 0; b < NB; b++)
#pragma unroll
        for (int mi = 0; mi < 4; mi++)
#pragma unroll
            for (int ni = 0; ni < 4; ni++)
#pragma unroll
                for (int q = 0; q < 4; q++) acc[b][mi][ni][q] = 0.0f;

    auto compute_stage = [&](int s) {
        const uint32_t st = sbase + (uint32_t)s * (uint32_t)(STAGE_FL * 4);
#pragma unroll
        for (int ks = 0; ks < 4; ks++) {
            uint32_t af[4][4];
#pragma unroll
            for (int mi = 0; mi < 4; mi++) {
                int row = wm * 64 + mi * 16 + (lane & 15);
                int gcs = (ks << 1) + (lane >> 4);
                uint32_t addr = st + ((uint32_t)((row << 5) + ((gcs ^ (row & 7)) << 2)) << 2);
                ldsm4(addr, af[mi][0], af[mi][1], af[mi][2], af[mi][3]);
            }
            uint32_t bf[NB][4][2];
#pragma unroll
            for (int b = 0; b < NB; b++) {
                uint32_t bt = st + 16384u + (uint32_t)b * 16384u;
#pragma unroll
                for (int p = 0; p < 2; p++) {
                    int row = wn * 32 + p * 16 + ((lane >> 4) << 3) + (lane & 7);
                    int gcs = (ks << 1) + ((lane >> 3) & 1);
                    uint32_t addr = bt + ((uint32_t)((row << 5) + ((gcs ^ (row & 7)) << 2)) << 2);
                    uint32_t r0, r1, r2, r3;
                    ldsm4(addr, r0, r1, r2, r3);
                    bf[b][2 * p][0] = cvt_tf32(r0);
                    bf[b][2 * p][1] = cvt_tf32(r1);
                    bf[b][2 * p + 1][0] = cvt_tf32(r2);
                    bf[b][2 * p + 1][1] = cvt_tf32(r3);
                }
            }
#pragma unroll
            for (int mi = 0; mi < 4; mi++)
#pragma unroll
                for (int q = 0; q < 4; q++) af[mi][q] = cvt_tf32(af[mi][q]);
#pragma unroll
            for (int b = 0; b < NB; b++)
#pragma unroll
                for (int mi = 0; mi < 4; mi++)
#pragma unroll
                    for (int ni = 0; ni < 4; ni++)
                        mma_tf32(acc[b][mi][ni], af[mi], bf[b][ni]);
        }
    };

    // pipeline
#pragma unroll
    for (int s = 0; s < STAGES - 1; s++) {
        load_stage(s, s * 32);
        cp_commit();
    }
    for (int kt = 0; kt < KT; kt++) {
        cp_wait<WAITN>();
        __syncthreads();
        int lk = kt + (STAGES - 1);
        if (lk < KT) load_stage(lk % STAGES, lk * 32);
        cp_commit();
        compute_stage(kt % STAGES);
    }
    cp_wait<0>();
    __syncthreads();

    // --- epilogue: stage low-rank tiles in smem (reuse stage 0) ---
    float* s_low = smem;          // [128][8]
    float* s_bl0 = smem + 1024;   // [128][8]
    float* s_bl1 = smem + 2048;   // [128][8] (NB==2)
    {
        int r_ = tid >> 1;
        int h4 = (tid & 1) * 4;
        ((float4*)s_low)[tid] = *(const float4*)(LOW + ((size_t)e * T_ + m0 + r_) * R_ + h4);
        ((float4*)s_bl0)[tid] =
            *(const float4*)(BL + ((size_t)e * NB * OUTS + n0 + r_) * R_ + h4);
        if constexpr (NB == 2)
            ((float4*)s_bl1)[tid] =
                *(const float4*)(BL + ((size_t)e * NB * OUTS + OUTS + n0 + r_) * R_ + h4);
    }
    __syncthreads();

    const int g = lane >> 2;
    const int tg = lane & 3;
#pragma unroll
    for (int mi = 0; mi < 4; mi++) {
#pragma unroll
        for (int rs = 0; rs < 2; rs++) {
            int lr = wm * 64 + mi * 16 + g + rs * 8;
            float lw[8];
#pragma unroll
            for (int r = 0; r < 8; r++) lw[r] = s_low[lr * 8 + r];
            float* orow = OUT + ((size_t)e * T_ + m0 + lr) * OUTS + n0;
#pragma unroll
            for (int ni = 0; ni < 4; ni++) {
                int lc = wn * 32 + ni * 8 + tg * 2;
                float v[2];
#pragma unroll
                for (int cc = 0; cc < 2; cc++) {
                    int col = lc + cc;
                    float dg = 0.0f;
#pragma unroll
                    for (int r = 0; r < 8; r++) dg += lw[r] * s_bl0[col * 8 + r];
                    float gv = acc[0][mi][ni][rs * 2 + cc] + SCALE_ * dg;
                    if constexpr (NB == 2) {
                        float du = 0.0f;
#pragma unroll
                        for (int r = 0; r < 8; r++) du += lw[r] * s_bl1[col * 8 + r];
                        float uv = acc[1][mi][ni][rs * 2 + cc] + SCALE_ * du;
                        // h = up * silu(gate)
                        v[cc] = uv * gv / (1.0f + __expf(-gv));
                    } else {
                        v[cc] = gv;
                    }
                }
                *(float2*)(orow + lc) = make_float2(v[0], v[1]);
            }
        }
    }
}

// ---------------------------------------------------------------------------
// Launch
// ---------------------------------------------------------------------------
extern "C" void kernel_launch(void* const* d_in, const int* in_sizes, int n_in,
                              void* d_out, int out_size) {
    (void)in_sizes; (void)n_in; (void)out_size;
    const float* x    = (const float*)d_in[0];
    const float* W_gu = (const float*)d_in[1];
    const float* A_gu = (const float*)d_in[2];
    const float* B_gu = (const float*)d_in[3];
    const float* W_d  = (const float*)d_in[4];
    const float* A_d  = (const float*)d_in[5];
    const float* B_d  = (const float*)d_in[6];
    float* out = (float*)d_out;

    const int smem1 = 3 * 3 * 4096 * 4;  // 3 stages * (A + Bg + Bu) = 147456 B
    const int smem2 = 3 * 2 * 4096 * 4;  // 3 stages * (A + B)       =  98304 B
    cudaFuncSetAttribute(gemm_tc_kernel<1>, cudaFuncAttributeMaxDynamicSharedMemorySize, smem1);
    cudaFuncSetAttribute(gemm_tc_kernel<2>, cudaFuncAttributeMaxDynamicSharedMemorySize, smem2);

    // 1) low_gu = x @ A_gu^T
    lora_low_kernel<0><<<dim3(T_ / 8, E_), 256>>>(x, A_gu);
    // 2) h = up * silu(gate), fused gate/up GEMM + LoRA + GLU epilogue
    gemm_tc_kernel<1><<<dim3(T_ / 128, D_ / 128, E_), 256, smem1>>>(x, W_gu, B_gu, nullptr);
    // 3) low_d = h @ A_d^T
    lora_low_kernel<1><<<dim3(T_ / 8, E_), 256>>>(nullptr, A_d);
    // 4) out = h @ W_d^T + SCALE * low_d @ B_d^T
    gemm_tc_kernel<2><<<dim3(T_ / 128, H_ / 128, E_), 256, smem2>>>(nullptr, W_d, B_d, out);
}

// round 4
// speedup vs baseline: 1.0151x; 1.0151x over previous
#include <cuda_runtime.h>
#include <cstdint>

// Problem constants
#define E_ 8
#define T_ 2048
#define H_ 2048
#define D_ 4096
#define R_ 8
#define SCALE_ 2.0f

// Scratch (allocation-free rule: __device__ globals)
__device__ float g_h[(size_t)E_ * T_ * D_];          // 256 MB intermediate h (tf32-rounded)
__device__ float g_xr[(size_t)E_ * T_ * H_];         // 64 MB  x rounded to tf32
__device__ float g_wgur[(size_t)E_ * 2 * D_ * H_];   // 512 MB W_gu rounded
__device__ float g_wdr[(size_t)E_ * H_ * D_];        // 256 MB W_d rounded
__device__ float g_low_gu[E_ * T_ * R_];
__device__ float g_low_d[E_ * T_ * R_];

// ---------------------------------------------------------------------------
// PTX helpers
// ---------------------------------------------------------------------------
__device__ __forceinline__ uint32_t smem_u32(const void* p) {
    return (uint32_t)__cvta_generic_to_shared(p);
}
__device__ __forceinline__ void cp_async16(uint32_t dst, const void* src) {
    asm volatile("cp.async.cg.shared.global [%0], [%1], 16;\n" :: "r"(dst), "l"(src));
}
__device__ __forceinline__ void cp_commit() {
    asm volatile("cp.async.commit_group;\n");
}
template <int N>
__device__ __forceinline__ void cp_wait() {
    asm volatile("cp.async.wait_group %0;\n" :: "n"(N));
}
__device__ __forceinline__ void ldsm4(uint32_t addr, uint32_t& r0, uint32_t& r1,
                                      uint32_t& r2, uint32_t& r3) {
    asm volatile("ldmatrix.sync.aligned.m8n8.x4.shared.b16 {%0,%1,%2,%3}, [%4];\n"
                 : "=r"(r0), "=r"(r1), "=r"(r2), "=r"(r3) : "r"(addr));
}
// fp32 -> tf32 round-to-nearest (RNA). Used ONLY in pre-pass / epilogue,
// never in the GEMM mainloop (HW truncation is exact on pre-rounded data).
__device__ __forceinline__ float rna_tf32(float x) {
    uint32_t d;
    asm("cvt.rna.tf32.f32 %0, %1;\n" : "=r"(d) : "f"(x));
    return __uint_as_float(d);
}
__device__ __forceinline__ void mma_tf32(float* c, const uint32_t* a, const uint32_t* b) {
    asm volatile(
        "mma.sync.aligned.m16n8k8.row.col.f32.tf32.tf32.f32 "
        "{%0,%1,%2,%3}, {%4,%5,%6,%7}, {%8,%9}, {%0,%1,%2,%3};\n"
        : "+f"(c[0]), "+f"(c[1]), "+f"(c[2]), "+f"(c[3])
        : "r"(a[0]), "r"(a[1]), "r"(a[2]), "r"(a[3]), "r"(b[0]), "r"(b[1]));
}

// ---------------------------------------------------------------------------
// tf32 pre-rounding (RNA), grid-stride, float4.
// ---------------------------------------------------------------------------
__global__ void __launch_bounds__(256) round_tf32_kernel(const float4* __restrict__ src,
                                                         float4* __restrict__ dst, int n4) {
    int i = blockIdx.x * blockDim.x + threadIdx.x;
    int stride = gridDim.x * blockDim.x;
    for (; i < n4; i += stride) {
        float4 v = src[i];
        v.x = rna_tf32(v.x); v.y = rna_tf32(v.y);
        v.z = rna_tf32(v.z); v.w = rna_tf32(v.w);
        dst[i] = v;
    }
}

// ---------------------------------------------------------------------------
// Rank-8 projection: LOW[e,t,r] = sum_k X[e,t,k] * A[e,r,k]   (fp32, exact)
// WHICH==0: X = hidden_states (K=H) -> g_low_gu; WHICH==1: X = g_h (K=D) -> g_low_d
// ---------------------------------------------------------------------------
template <int WHICH>
__global__ void __launch_bounds__(256) lora_low_kernel(const float* __restrict__ xin,
                                                       const float* __restrict__ Ain) {
    constexpr int K = (WHICH == 0) ? H_ : D_;
    constexpr int K4 = K / 4;
    const float* X = (WHICH == 0) ? xin : g_h;
    float* LOWOUT = (WHICH == 0) ? g_low_gu : g_low_d;

    const int e = blockIdx.y;
    const int wid = threadIdx.x >> 5;
    const int lane = threadIdx.x & 31;
    const int t = blockIdx.x * 8 + wid;

    const float4* x4 = (const float4*)(X + ((size_t)e * T_ + t) * K);
    const float4* a4 = (const float4*)(Ain + (size_t)e * R_ * K);

    float acc[R_];
#pragma unroll
    for (int r = 0; r < R_; r++) acc[r] = 0.0f;

    for (int k = lane; k < K4; k += 32) {
        float4 xv = x4[k];
#pragma unroll
        for (int r = 0; r < R_; r++) {
            float4 av = a4[(size_t)r * K4 + k];
            acc[r] += xv.x * av.x + xv.y * av.y + xv.z * av.z + xv.w * av.w;
        }
    }
#pragma unroll
    for (int r = 0; r < R_; r++) {
#pragma unroll
        for (int off = 16; off > 0; off >>= 1)
            acc[r] += __shfl_xor_sync(0xffffffffu, acc[r], off);
    }
    if (lane == 0) {
        float* dst = LOWOUT + ((size_t)e * T_ + t) * R_;
#pragma unroll
        for (int r = 0; r < R_; r++) dst[r] = acc[r];
    }
}

// ---------------------------------------------------------------------------
// Tiled TF32 tensor-core GEMM with LoRA epilogue. Operands are PRE-ROUNDED to
// tf32 (RNA) in gmem, so the mainloop feeds raw bits into mma.sync (no cvt).
// PHASE==1: fused gate/up GEMM + SiLU-mul -> g_h    (K=H, N=D, NB=2 B-tiles)
// PHASE==2: down GEMM -> out                        (K=D, N=H, NB=1)
// CTA tile 128x128, BK=32, 8 warps (2x4), warp tile 64x32, cp.async pipeline.
// Smem XOR swizzle: 16B granule gc stored at gc ^ (row&7) -> conflict-free ldmatrix.
// ---------------------------------------------------------------------------
template <int PHASE>
__global__ void __launch_bounds__(256, (PHASE == 1) ? 1 : 2) gemm_tc_kernel(
    const float* __restrict__ W, const float* __restrict__ BL,
    float* __restrict__ outp) {
    constexpr int KD = (PHASE == 1) ? H_ : D_;
    constexpr int OUTS = (PHASE == 1) ? D_ : H_;
    constexpr int NB = (PHASE == 1) ? 2 : 1;
    constexpr int KT = KD / 32;
    constexpr int STAGES = 3;
    constexpr int WAITN = STAGES - 2;
    constexpr int STAGE_FL = 4096 * (1 + NB);

    extern __shared__ float smem[];

    const float* Ain = (PHASE == 1) ? g_xr : g_h;
    const float* LOW = (PHASE == 1) ? g_low_gu : g_low_d;
    float* OUT = (PHASE == 1) ? g_h : outp;

    const int e = blockIdx.z;
    const int m0 = blockIdx.x * 128;
    const int n0 = blockIdx.y * 128;

    const int tid = threadIdx.x;
    const int lane = tid & 31;
    const int wid = tid >> 5;
    const int wm = wid & 1;
    const int wn = wid >> 1;

    const float* Abase = Ain + ((size_t)e * T_ + m0) * KD;
    const float* Wb0 = W + ((size_t)e * NB * OUTS + n0) * KD;          // gate / down rows
    const float* Wb1 = W + ((size_t)e * NB * OUTS + OUTS + n0) * KD;   // up rows (NB==2)

    const uint32_t sbase = smem_u32(smem);

    auto load_stage = [&](int s, int k0) {
        const uint32_t st = sbase + (uint32_t)s * (uint32_t)(STAGE_FL * 4);
#pragma unroll
        for (int i = 0; i < 4; i++) {
            int gi = tid + i * 256;          // 1024 granules (128 rows x 8)
            int row = gi >> 3;
            int gc = gi & 7;
            uint32_t soff = (uint32_t)((row << 5) + ((gc ^ (row & 7)) << 2)) << 2;
            size_t goff = (size_t)row * KD + (k0 + (gc << 2));
            cp_async16(st + soff, Abase + goff);
            cp_async16(st + 16384u + soff, Wb0 + goff);
            if constexpr (NB == 2) cp_async16(st + 32768u + soff, Wb1 + goff);
        }
    };

    float acc[NB][4][4][4];
#pragma unroll
    for (int b = 0; b < NB; b++)
#pragma unroll
        for (int mi = 0; mi < 4; mi++)
#pragma unroll
            for (int ni = 0; ni < 4; ni++)
#pragma unroll
                for (int q = 0; q < 4; q++) acc[b][mi][ni][q] = 0.0f;

    auto compute_stage = [&](int s) {
        const uint32_t st = sbase + (uint32_t)s * (uint32_t)(STAGE_FL * 4);
#pragma unroll
        for (int ks = 0; ks < 4; ks++) {
            uint32_t af[4][4];
#pragma unroll
            for (int mi = 0; mi < 4; mi++) {
                int row = wm * 64 + mi * 16 + (lane & 15);
                int gcs = (ks << 1) + (lane >> 4);
                uint32_t addr = st + ((uint32_t)((row << 5) + ((gcs ^ (row & 7)) << 2)) << 2);
                ldsm4(addr, af[mi][0], af[mi][1], af[mi][2], af[mi][3]);
            }
            uint32_t bf[NB][4][2];
#pragma unroll
            for (int b = 0; b < NB; b++) {
                uint32_t bt = st + 16384u + (uint32_t)b * 16384u;
#pragma unroll
                for (int p = 0; p < 2; p++) {
                    int row = wn * 32 + p * 16 + ((lane >> 4) << 3) + (lane & 7);
                    int gcs = (ks << 1) + ((lane >> 3) & 1);
                    uint32_t addr = bt + ((uint32_t)((row << 5) + ((gcs ^ (row & 7)) << 2)) << 2);
                    ldsm4(addr, bf[b][2 * p][0], bf[b][2 * p][1],
                          bf[b][2 * p + 1][0], bf[b][2 * p + 1][1]);
                }
            }
            // No cvt: operands pre-rounded to tf32-RNA; HW truncation is exact.
#pragma unroll
            for (int b = 0; b < NB; b++)
#pragma unroll
                for (int mi = 0; mi < 4; mi++)
#pragma unroll
                    for (int ni = 0; ni < 4; ni++)
                        mma_tf32(acc[b][mi][ni], af[mi], bf[b][ni]);
        }
    };

    // pipeline
#pragma unroll
    for (int s = 0; s < STAGES - 1; s++) {
        load_stage(s, s * 32);
        cp_commit();
    }
    for (int kt = 0; kt < KT; kt++) {
        cp_wait<WAITN>();
        __syncthreads();
        int lk = kt + (STAGES - 1);
        if (lk < KT) load_stage(lk % STAGES, lk * 32);
        cp_commit();
        compute_stage(kt % STAGES);
    }
    cp_wait<0>();
    __syncthreads();

    // --- epilogue: stage low-rank tiles in smem (reuse stage 0) ---
    float* s_low = smem;          // [128][8]
    float* s_bl0 = smem + 1024;   // [128][8]
    float* s_bl1 = smem + 2048;   // [128][8] (NB==2)
    {
        int r_ = tid >> 1;
        int h4 = (tid & 1) * 4;
        ((float4*)s_low)[tid] = *(const float4*)(LOW + ((size_t)e * T_ + m0 + r_) * R_ + h4);
        ((float4*)s_bl0)[tid] =
            *(const float4*)(BL + ((size_t)e * NB * OUTS + n0 + r_) * R_ + h4);
        if constexpr (NB == 2)
            ((float4*)s_bl1)[tid] =
                *(const float4*)(BL + ((size_t)e * NB * OUTS + OUTS + n0 + r_) * R_ + h4);
    }
    __syncthreads();

    const int g = lane >> 2;
    const int tg = lane & 3;
#pragma unroll
    for (int mi = 0; mi < 4; mi++) {
#pragma unroll
        for (int rs = 0; rs < 2; rs++) {
            int lr = wm * 64 + mi * 16 + g + rs * 8;
            float lw[8];
#pragma unroll
            for (int r = 0; r < 8; r++) lw[r] = s_low[lr * 8 + r];
            float* orow = OUT + ((size_t)e * T_ + m0 + lr) * OUTS + n0;
#pragma unroll
            for (int ni = 0; ni < 4; ni++) {
                int lc = wn * 32 + ni * 8 + tg * 2;
                float v[2];
#pragma unroll
                for (int cc = 0; cc < 2; cc++) {
                    int col = lc + cc;
                    float dg = 0.0f;
#pragma unroll
                    for (int r = 0; r < 8; r++) dg += lw[r] * s_bl0[col * 8 + r];
                    float gv = acc[0][mi][ni][rs * 2 + cc] + SCALE_ * dg;
                    if constexpr (NB == 2) {
                        float du = 0.0f;
#pragma unroll
                        for (int r = 0; r < 8; r++) du += lw[r] * s_bl1[col * 8 + r];
                        float uv = acc[1][mi][ni][rs * 2 + cc] + SCALE_ * du;
                        // h = up * silu(gate), pre-rounded to tf32 for phase 2
                        v[cc] = rna_tf32(uv * gv / (1.0f + __expf(-gv)));
                    } else {
                        v[cc] = gv;
                    }
                }
                *(float2*)(orow + lc) = make_float2(v[0], v[1]);
            }
        }
    }
}

// ---------------------------------------------------------------------------
// Launch
// ---------------------------------------------------------------------------
extern "C" void kernel_launch(void* const* d_in, const int* in_sizes, int n_in,
                              void* d_out, int out_size) {
    (void)in_sizes; (void)n_in; (void)out_size;
    const float* x    = (const float*)d_in[0];
    const float* W_gu = (const float*)d_in[1];
    const float* A_gu = (const float*)d_in[2];
    const float* B_gu = (const float*)d_in[3];
    const float* W_d  = (const float*)d_in[4];
    const float* A_d  = (const float*)d_in[5];
    const float* B_d  = (const float*)d_in[6];
    float* out = (float*)d_out;

    static float* p_xr = nullptr;
    static float* p_wgur = nullptr;
    static float* p_wdr = nullptr;
    if (!p_xr) {  // symbol address lookups (not allocations); idempotent
        cudaGetSymbolAddress((void**)&p_xr, g_xr);
        cudaGetSymbolAddress((void**)&p_wgur, g_wgur);
        cudaGetSymbolAddress((void**)&p_wdr, g_wdr);
        const int smem1 = 3 * 3 * 4096 * 4;  // 147456 B
        const int smem2 = 3 * 2 * 4096 * 4;  //  98304 B
        cudaFuncSetAttribute(gemm_tc_kernel<1>,
                             cudaFuncAttributeMaxDynamicSharedMemorySize, smem1);
        cudaFuncSetAttribute(gemm_tc_kernel<2>,
                             cudaFuncAttributeMaxDynamicSharedMemorySize, smem2);
    }

    // 0) pre-round operands to tf32 (RNA): mainloop then needs no cvt at all
    round_tf32_kernel<<<2048, 256>>>((const float4*)x, (float4*)p_xr,
                                     E_ * T_ * H_ / 4);
    round_tf32_kernel<<<8192, 256>>>((const float4*)W_gu, (float4*)p_wgur,
                                     E_ * 2 * D_ * (H_ / 4));
    round_tf32_kernel<<<8192, 256>>>((const float4*)W_d, (float4*)p_wdr,
                                     E_ * H_ * (D_ / 4));

    // 1) low_gu = x @ A_gu^T (exact fp32 on original x)
    lora_low_kernel<0><<<dim3(T_ / 8, E_), 256>>>(x, A_gu);
    // 2) h = up * silu(gate): fused gate/up GEMM + LoRA + GLU epilogue
    gemm_tc_kernel<1><<<dim3(T_ / 128, D_ / 128, E_), 256, 3 * 3 * 4096 * 4>>>(
        p_wgur, B_gu, nullptr);
    // 3) low_d = h @ A_d^T
    lora_low_kernel<1><<<dim3(T_ / 8, E_), 256>>>(nullptr, A_d);
    // 4) out = h @ W_d^T + SCALE * low_d @ B_d^T
    gemm_tc_kernel<2><<<dim3(T_ / 128, H_ / 128, E_), 256, 3 * 2 * 4096 * 4>>>(
        p_wdr, B_d, out);
}

// round 11
// speedup vs baseline: 1.7942x; 1.7676x over previous
#include <cuda_runtime.h>
#include <cuda_fp16.h>
#include <cstdint>

// Problem constants
#define E_ 8
#define T_ 2048
#define H_ 2048
#define D_ 4096
#define R_ 8
#define SCALE_ 2.0f

// Scratch (allocation-free rule: __device__ globals). fp16 operand copies.
__device__ __half g_hh[(size_t)E_ * T_ * D_];          // 134 MB intermediate h (fp16)
__device__ __half g_xh[(size_t)E_ * T_ * H_];          // 67 MB  x (fp16)
__device__ __half g_wguh[(size_t)E_ * 2 * D_ * H_];    // 268 MB W_gu (fp16)
__device__ __half g_wdh[(size_t)E_ * H_ * D_];         // 134 MB W_d (fp16)
__device__ float g_low_gu[E_ * T_ * R_];
__device__ float g_low_d[E_ * T_ * R_];

// ---------------------------------------------------------------------------
// PTX helpers
// ---------------------------------------------------------------------------
__device__ __forceinline__ uint32_t smem_u32(const void* p) {
    return (uint32_t)__cvta_generic_to_shared(p);
}
__device__ __forceinline__ void cp_async16(uint32_t dst, const void* src) {
    asm volatile("cp.async.cg.shared.global [%0], [%1], 16;\n" :: "r"(dst), "l"(src));
}
__device__ __forceinline__ void cp_commit() {
    asm volatile("cp.async.commit_group;\n");
}
template <int N>
__device__ __forceinline__ void cp_wait() {
    asm volatile("cp.async.wait_group %0;\n" :: "n"(N));
}
__device__ __forceinline__ void ldsm4(uint32_t addr, uint32_t& r0, uint32_t& r1,
                                      uint32_t& r2, uint32_t& r3) {
    asm volatile("ldmatrix.sync.aligned.m8n8.x4.shared.b16 {%0,%1,%2,%3}, [%4];\n"
                 : "=r"(r0), "=r"(r1), "=r"(r2), "=r"(r3) : "r"(addr));
}
// fp16 mma, fp32 accumulate. Same mantissa width as tf32, 2x the rate.
__device__ __forceinline__ void mma_f16(float* c, const uint32_t* a, const uint32_t* b) {
    asm volatile(
        "mma.sync.aligned.m16n8k16.row.col.f32.f16.f16.f32 "
        "{%0,%1,%2,%3}, {%4,%5,%6,%7}, {%8,%9}, {%0,%1,%2,%3};\n"
        : "+f"(c[0]), "+f"(c[1]), "+f"(c[2]), "+f"(c[3])
        : "r"(a[0]), "r"(a[1]), "r"(a[2]), "r"(a[3]), "r"(b[0]), "r"(b[1]));
}

// ---------------------------------------------------------------------------
// fp32 -> fp16 (RNE) pre-rounding, 8 floats per thread-iteration.
// ---------------------------------------------------------------------------
__global__ void __launch_bounds__(256) round_half_kernel(const float4* __restrict__ src,
                                                         uint4* __restrict__ dst, int n8) {
    int i = blockIdx.x * blockDim.x + threadIdx.x;
    int stride = gridDim.x * blockDim.x;
    for (; i < n8; i += stride) {
        float4 v0 = src[2 * i];
        float4 v1 = src[2 * i + 1];
        __half2 h0 = __floats2half2_rn(v0.x, v0.y);
        __half2 h1 = __floats2half2_rn(v0.z, v0.w);
        __half2 h2 = __floats2half2_rn(v1.x, v1.y);
        __half2 h3 = __floats2half2_rn(v1.z, v1.w);
        uint4 o;
        o.x = *(uint32_t*)&h0; o.y = *(uint32_t*)&h1;
        o.z = *(uint32_t*)&h2; o.w = *(uint32_t*)&h3;
        dst[i] = o;
    }
}

// ---------------------------------------------------------------------------
// Rank-8 projection: LOW[e,t,r] = sum_k X[e,t,k] * A[e,r,k]   (fp32 accum)
// WHICH==0: X = hidden_states fp32 (K=H) -> g_low_gu
// WHICH==1: X = g_hh fp16        (K=D) -> g_low_d
// ---------------------------------------------------------------------------
template <int WHICH>
__global__ void __launch_bounds__(256) lora_low_kernel(const float* __restrict__ xin,
                                                       const float* __restrict__ Ain) {
    constexpr int K = (WHICH == 0) ? H_ : D_;
    float* LOWOUT = (WHICH == 0) ? g_low_gu : g_low_d;

    const int e = blockIdx.y;
    const int wid = threadIdx.x >> 5;
    const int lane = threadIdx.x & 31;
    const int t = blockIdx.x * 8 + wid;

    float acc[R_];
#pragma unroll
    for (int r = 0; r < R_; r++) acc[r] = 0.0f;

    if constexpr (WHICH == 0) {
        const float4* x4 = (const float4*)(xin + ((size_t)e * T_ + t) * K);
        const float4* a4 = (const float4*)(Ain + (size_t)e * R_ * K);
        for (int k = lane; k < K / 4; k += 32) {
            float4 xv = x4[k];
#pragma unroll
            for (int r = 0; r < R_; r++) {
                float4 av = a4[(size_t)r * (K / 4) + k];
                acc[r] += xv.x * av.x + xv.y * av.y + xv.z * av.z + xv.w * av.w;
            }
        }
    } else {
        const uint4* x8 = (const uint4*)(g_hh + ((size_t)e * T_ + t) * K);
        const float4* a4 = (const float4*)(Ain + (size_t)e * R_ * K);
        for (int k8 = lane; k8 < K / 8; k8 += 32) {
            uint4 u = x8[k8];
            float2 f0 = __half22float2(*(__half2*)&u.x);
            float2 f1 = __half22float2(*(__half2*)&u.y);
            float2 f2 = __half22float2(*(__half2*)&u.z);
            float2 f3 = __half22float2(*(__half2*)&u.w);
#pragma unroll
            for (int r = 0; r < R_; r++) {
                float4 a0 = a4[(size_t)r * (K / 4) + 2 * k8];
                float4 a1 = a4[(size_t)r * (K / 4) + 2 * k8 + 1];
                acc[r] += f0.x * a0.x + f0.y * a0.y + f1.x * a0.z + f1.y * a0.w +
                          f2.x * a1.x + f2.y * a1.y + f3.x * a1.z + f3.y * a1.w;
            }
        }
    }
#pragma unroll
    for (int r = 0; r < R_; r++) {
#pragma unroll
        for (int off = 16; off > 0; off >>= 1)
            acc[r] += __shfl_xor_sync(0xffffffffu, acc[r], off);
    }
    if (lane == 0) {
        float* dst = LOWOUT + ((size_t)e * T_ + t) * R_;
#pragma unroll
        for (int r = 0; r < R_; r++) dst[r] = acc[r];
    }
}

// ---------------------------------------------------------------------------
// Tiled FP16 tensor-core GEMM with LoRA epilogue. Operands pre-rounded to
// fp16-RNE in gmem; fp32 accumulation; mma.sync.m16n8k16.
// PHASE==1: fused gate/up GEMM + SiLU-mul -> g_hh (half)  (K=H, N=D, NB=2)
// PHASE==2: down GEMM -> out (fp32)                       (K=D, N=H, NB=1)
// CTA tile 128x128, BK=64 (128B rows of fp16), 8 warps (2x4), warp tile 64x32.
// Smem XOR swizzle on 16B granules: gc ^ (row&7) -> conflict-free ldmatrix.
// ---------------------------------------------------------------------------
template <int PHASE>
__global__ void __launch_bounds__(256, (PHASE == 1) ? 1 : 2) gemm_tc_kernel(
    const __half* __restrict__ W, const float* __restrict__ BL,
    float* __restrict__ outp) {
    constexpr int KD = (PHASE == 1) ? H_ : D_;
    constexpr int OUTS = (PHASE == 1) ? D_ : H_;
    constexpr int NB = (PHASE == 1) ? 2 : 1;
    constexpr int KT = KD / 64;
    constexpr int STAGES = 3;
    constexpr int WAITN = STAGES - 2;
    constexpr int STAGE_BYTES = 16384 * (1 + NB);   // 16KB per 128x64-fp16 tile

    extern __shared__ float smem[];

    const __half* Ain = (PHASE == 1) ? g_xh : g_hh;
    const float* LOW = (PHASE == 1) ? g_low_gu : g_low_d;

    const int e = blockIdx.z;
    const int m0 = blockIdx.x * 128;
    const int n0 = blockIdx.y * 128;

    const int tid = threadIdx.x;
    const int lane = tid & 31;
    const int wid = tid >> 5;
    const int wm = wid & 1;
    const int wn = wid >> 1;

    const __half* Abase = Ain + ((size_t)e * T_ + m0) * KD;
    const __half* Wb0 = W + ((size_t)e * NB * OUTS + n0) * KD;          // gate / down
    const __half* Wb1 = W + ((size_t)e * NB * OUTS + OUTS + n0) * KD;   // up (NB==2)

    const uint32_t sbase = smem_u32(smem);

    auto load_stage = [&](int s, int k0) {
        const uint32_t st = sbase + (uint32_t)s * (uint32_t)STAGE_BYTES;
#pragma unroll
        for (int i = 0; i < 4; i++) {
            int gi = tid + i * 256;          // 1024 granules (128 rows x 8 x 16B)
            int row = gi >> 3;
            int gc = gi & 7;
            uint32_t soff = (uint32_t)(row * 128 + ((gc ^ (row & 7)) << 4));
            size_t goff = (size_t)row * KD + (k0 + (gc << 3));   // 8 halfs/granule
            cp_async16(st + soff, Abase + goff);
            cp_async16(st + 16384u + soff, Wb0 + goff);
            if constexpr (NB == 2) cp_async16(st + 32768u + soff, Wb1 + goff);
        }
    };

    float acc[NB][4][4][4];
#pragma unroll
    for (int b = 0; b < NB; b++)
#pragma unroll
        for (int mi = 0; mi < 4; mi++)
#pragma unroll
            for (int ni = 0; ni < 4; ni++)
#pragma unroll
                for (int q = 0; q < 4; q++) acc[b][mi][ni][q] = 0.0f;

    auto compute_stage = [&](int s) {
        const uint32_t st = sbase + (uint32_t)s * (uint32_t)STAGE_BYTES;
#pragma unroll
        for (int ks = 0; ks < 4; ks++) {     // 4 x k16 = BK 64
            uint32_t af[4][4];
#pragma unroll
            for (int mi = 0; mi < 4; mi++) {
                int row = wm * 64 + mi * 16 + (lane & 15);
                int gcs = (ks << 1) + (lane >> 4);
                uint32_t addr = st + (uint32_t)(row * 128 + ((gcs ^ (row & 7)) << 4));
                ldsm4(addr, af[mi][0], af[mi][1], af[mi][2], af[mi][3]);
            }
            uint32_t bf[NB][4][2];
#pragma unroll
            for (int b = 0; b < NB; b++) {
                uint32_t bt = st + 16384u + (uint32_t)b * 16384u;
#pragma unroll
                for (int p = 0; p < 2; p++) {
                    int row = wn * 32 + p * 16 + ((lane >> 4) << 3) + (lane & 7);
                    int gcs = (ks << 1) + ((lane >> 3) & 1);
                    uint32_t addr = bt + (uint32_t)(row * 128 + ((gcs ^ (row & 7)) << 4));
                    ldsm4(addr, bf[b][2 * p][0], bf[b][2 * p][1],
                          bf[b][2 * p + 1][0], bf[b][2 * p + 1][1]);
                }
            }
#pragma unroll
            for (int b = 0; b < NB; b++)
#pragma unroll
                for (int mi = 0; mi < 4; mi++)
#pragma unroll
                    for (int ni = 0; ni < 4; ni++)
                        mma_f16(acc[b][mi][ni], af[mi], bf[b][ni]);
        }
    };

    // pipeline
#pragma unroll
    for (int s = 0; s < STAGES - 1; s++) {
        load_stage(s, s * 64);
        cp_commit();
    }
    for (int kt = 0; kt < KT; kt++) {
        cp_wait<WAITN>();
        __syncthreads();
        int lk = kt + (STAGES - 1);
        if (lk < KT) load_stage(lk % STAGES, lk * 64);
        cp_commit();
        compute_stage(kt % STAGES);
    }
    cp_wait<0>();
    __syncthreads();

    // --- epilogue: stage low-rank tiles in smem (reuse stage 0) ---
    float* s_low = smem;          // [128][8]
    float* s_bl0 = smem + 1024;   // [128][8]
    float* s_bl1 = smem + 2048;   // [128][8] (NB==2)
    {
        int r_ = tid >> 1;
        int h4 = (tid & 1) * 4;
        ((float4*)s_low)[tid] = *(const float4*)(LOW + ((size_t)e * T_ + m0 + r_) * R_ + h4);
        ((float4*)s_bl0)[tid] =
            *(const float4*)(BL + ((size_t)e * NB * OUTS + n0 + r_) * R_ + h4);
        if constexpr (NB == 2)
            ((float4*)s_bl1)[tid] =
                *(const float4*)(BL + ((size_t)e * NB * OUTS + OUTS + n0 + r_) * R_ + h4);
    }
    __syncthreads();

    const int g = lane >> 2;
    const int tg = lane & 3;
#pragma unroll
    for (int mi = 0; mi < 4; mi++) {
#pragma unroll
        for (int rs = 0; rs < 2; rs++) {
            int lr = wm * 64 + mi * 16 + g + rs * 8;
            float lw[8];
#pragma unroll
            for (int r = 0; r < 8; r++) lw[r] = s_low[lr * 8 + r];
#pragma unroll
            for (int ni = 0; ni < 4; ni++) {
                int lc = wn * 32 + ni * 8 + tg * 2;
                float v[2];
#pragma unroll
                for (int cc = 0; cc < 2; cc++) {
                    int col = lc + cc;
                    float dg = 0.0f;
#pragma unroll
                    for (int r = 0; r < 8; r++) dg += lw[r] * s_bl0[col * 8 + r];
                    float gv = acc[0][mi][ni][rs * 2 + cc] + SCALE_ * dg;
                    if constexpr (NB == 2) {
                        float du = 0.0f;
#pragma unroll
                        for (int r = 0; r < 8; r++) du += lw[r] * s_bl1[col * 8 + r];
                        float uv = acc[1][mi][ni][rs * 2 + cc] + SCALE_ * du;
                        v[cc] = uv * gv / (1.0f + __expf(-gv));   // h = up*silu(gate)
                    } else {
                        v[cc] = gv;
                    }
                }
                if constexpr (PHASE == 1) {
                    __half* orow = g_hh + ((size_t)e * T_ + m0 + lr) * OUTS + n0;
                    *(__half2*)(orow + lc) = __floats2half2_rn(v[0], v[1]);
                } else {
                    float* orow = outp + ((size_t)e * T_ + m0 + lr) * OUTS + n0;
                    *(float2*)(orow + lc) = make_float2(v[0], v[1]);
                }
            }
        }
    }
}

// ---------------------------------------------------------------------------
// Launch
// ---------------------------------------------------------------------------
extern "C" void kernel_launch(void* const* d_in, const int* in_sizes, int n_in,
                              void* d_out, int out_size) {
    (void)in_sizes; (void)n_in; (void)out_size;
    const float* x    = (const float*)d_in[0];
    const float* W_gu = (const float*)d_in[1];
    const float* A_gu = (const float*)d_in[2];
    const float* B_gu = (const float*)d_in[3];
    const float* W_d  = (const float*)d_in[4];
    const float* A_d  = (const float*)d_in[5];
    const float* B_d  = (const float*)d_in[6];
    float* out = (float*)d_out;

    static __half* p_xh = nullptr;
    static __half* p_wguh = nullptr;
    static __half* p_wdh = nullptr;
    if (!p_xh) {  // symbol address lookups (not allocations); idempotent
        cudaGetSymbolAddress((void**)&p_xh, g_xh);
        cudaGetSymbolAddress((void**)&p_wguh, g_wguh);
        cudaGetSymbolAddress((void**)&p_wdh, g_wdh);
        const int smem1 = 3 * 3 * 16384;  // 147456 B
        const int smem2 = 3 * 2 * 16384;  //  98304 B
        cudaFuncSetAttribute(gemm_tc_kernel<1>,
                             cudaFuncAttributeMaxDynamicSharedMemorySize, smem1);
        cudaFuncSetAttribute(gemm_tc_kernel<2>,
                             cudaFuncAttributeMaxDynamicSharedMemorySize, smem2);
    }

    // 0) pre-round operands to fp16 (RNE); GEMM mainloop then runs raw fp16 mma
    round_half_kernel<<<2048, 256>>>((const float4*)x, (uint4*)p_xh,
                                     E_ * T_ * H_ / 8);
    round_half_kernel<<<8192, 256>>>((const float4*)W_gu, (uint4*)p_wguh,
                                     E_ * 2 * D_ * (H_ / 8));
    round_half_kernel<<<8192, 256>>>((const float4*)W_d, (uint4*)p_wdh,
                                     E_ * H_ * (D_ / 8));

    // 1) low_gu = x @ A_gu^T (fp32 on original x)
    lora_low_kernel<0><<<dim3(T_ / 8, E_), 256>>>(x, A_gu);
    // 2) h = up * silu(gate): fused gate/up GEMM + LoRA + GLU epilogue -> g_hh
    gemm_tc_kernel<1><<<dim3(T_ / 128, D_ / 128, E_), 256, 3 * 3 * 16384>>>(
        p_wguh, B_gu, nullptr);
    // 3) low_d = h @ A_d^T
    lora_low_kernel<1><<<dim3(T_ / 8, E_), 256>>>(nullptr, A_d);
    // 4) out = h @ W_d^T + SCALE * low_d @ B_d^T
    gemm_tc_kernel<2><<<dim3(T_ / 128, H_ / 128, E_), 256, 3 * 2 * 16384>>>(
        p_wdh, B_d, out);
}

// round 13
// speedup vs baseline: 1.8980x; 1.0578x over previous
#include <cuda_runtime.h>
#include <cuda_fp16.h>
#include <cstdint>

// Problem constants
#define E_ 8
#define T_ 2048
#define H_ 2048
#define D_ 4096
#define R_ 8
#define SCALE_ 2.0f

// Scratch (allocation-free rule: __device__ globals). fp16 operand copies.
__device__ __half g_hh[(size_t)E_ * T_ * D_];          // 134 MB intermediate h (fp16)
__device__ __half g_xh[(size_t)E_ * T_ * H_];          // 67 MB  x (fp16)
__device__ __half g_wguh[(size_t)E_ * 2 * D_ * H_];    // 268 MB W_gu (fp16)
__device__ __half g_wdh[(size_t)E_ * H_ * D_];         // 134 MB W_d (fp16)
__device__ float g_low_gu[E_ * T_ * R_];
__device__ float g_low_d[E_ * T_ * R_];

// ---------------------------------------------------------------------------
// PTX helpers
// ---------------------------------------------------------------------------
__device__ __forceinline__ uint32_t smem_u32(const void* p) {
    return (uint32_t)__cvta_generic_to_shared(p);
}
__device__ __forceinline__ void cp_async16(uint32_t dst, const void* src) {
    asm volatile("cp.async.cg.shared.global [%0], [%1], 16;\n" :: "r"(dst), "l"(src));
}
__device__ __forceinline__ void cp_commit() {
    asm volatile("cp.async.commit_group;\n");
}
template <int N>
__device__ __forceinline__ void cp_wait() {
    asm volatile("cp.async.wait_group %0;\n" :: "n"(N));
}
__device__ __forceinline__ void ldsm4(uint32_t addr, uint32_t& r0, uint32_t& r1,
                                      uint32_t& r2, uint32_t& r3) {
    asm volatile("ldmatrix.sync.aligned.m8n8.x4.shared.b16 {%0,%1,%2,%3}, [%4];\n"
                 : "=r"(r0), "=r"(r1), "=r"(r2), "=r"(r3) : "r"(addr));
}
// fp16 mma, fp32 accumulate.
__device__ __forceinline__ void mma_f16(float* c, const uint32_t* a, const uint32_t* b) {
    asm volatile(
        "mma.sync.aligned.m16n8k16.row.col.f32.f16.f16.f32 "
        "{%0,%1,%2,%3}, {%4,%5,%6,%7}, {%8,%9}, {%0,%1,%2,%3};\n"
        : "+f"(c[0]), "+f"(c[1]), "+f"(c[2]), "+f"(c[3])
        : "r"(a[0]), "r"(a[1]), "r"(a[2]), "r"(a[3]), "r"(b[0]), "r"(b[1]));
}

// ---------------------------------------------------------------------------
// fp32 -> fp16 (RNE) pre-rounding, 8 floats per thread-iteration.
// ---------------------------------------------------------------------------
__global__ void __launch_bounds__(256) round_half_kernel(const float4* __restrict__ src,
                                                         uint4* __restrict__ dst, int n8) {
    int i = blockIdx.x * blockDim.x + threadIdx.x;
    int stride = gridDim.x * blockDim.x;
    for (; i < n8; i += stride) {
        float4 v0 = src[2 * i];
        float4 v1 = src[2 * i + 1];
        __half2 h0 = __floats2half2_rn(v0.x, v0.y);
        __half2 h1 = __floats2half2_rn(v0.z, v0.w);
        __half2 h2 = __floats2half2_rn(v1.x, v1.y);
        __half2 h3 = __floats2half2_rn(v1.z, v1.w);
        uint4 o;
        o.x = *(uint32_t*)&h0; o.y = *(uint32_t*)&h1;
        o.z = *(uint32_t*)&h2; o.w = *(uint32_t*)&h3;
        dst[i] = o;
    }
}

// ---------------------------------------------------------------------------
// Rank-8 projection: LOW[e,t,r] = sum_k X[e,t,k] * A[e,r,k]   (fp32 accum)
// X is fp16 (WHICH==0: g_xh, K=H -> g_low_gu; WHICH==1: g_hh, K=D -> g_low_d).
// A stays fp32. Error in the rank-8 delta term is diluted ~100x in the output.
// ---------------------------------------------------------------------------
template <int WHICH>
__global__ void __launch_bounds__(256) lora_low_kernel(const float* __restrict__ Ain) {
    constexpr int K = (WHICH == 0) ? H_ : D_;
    const __half* X = (WHICH == 0) ? g_xh : g_hh;
    float* LOWOUT = (WHICH == 0) ? g_low_gu : g_low_d;

    const int e = blockIdx.y;
    const int wid = threadIdx.x >> 5;
    const int lane = threadIdx.x & 31;
    const int t = blockIdx.x * 8 + wid;

    float acc[R_];
#pragma unroll
    for (int r = 0; r < R_; r++) acc[r] = 0.0f;

    const uint4* x8 = (const uint4*)(X + ((size_t)e * T_ + t) * K);
    const float4* a4 = (const float4*)(Ain + (size_t)e * R_ * K);
    for (int k8 = lane; k8 < K / 8; k8 += 32) {
        uint4 u = x8[k8];
        float2 f0 = __half22float2(*(__half2*)&u.x);
        float2 f1 = __half22float2(*(__half2*)&u.y);
        float2 f2 = __half22float2(*(__half2*)&u.z);
        float2 f3 = __half22float2(*(__half2*)&u.w);
#pragma unroll
        for (int r = 0; r < R_; r++) {
            float4 a0 = a4[(size_t)r * (K / 4) + 2 * k8];
            float4 a1 = a4[(size_t)r * (K / 4) + 2 * k8 + 1];
            acc[r] += f0.x * a0.x + f0.y * a0.y + f1.x * a0.z + f1.y * a0.w +
                      f2.x * a1.x + f2.y * a1.y + f3.x * a1.z + f3.y * a1.w;
        }
    }
#pragma unroll
    for (int r = 0; r < R_; r++) {
#pragma unroll
        for (int off = 16; off > 0; off >>= 1)
            acc[r] += __shfl_xor_sync(0xffffffffu, acc[r], off);
    }
    if (lane == 0) {
        float* dst = LOWOUT + ((size_t)e * T_ + t) * R_;
#pragma unroll
        for (int r = 0; r < R_; r++) dst[r] = acc[r];
    }
}

// ---------------------------------------------------------------------------
// Tiled FP16 tensor-core GEMM with LoRA epilogue (operands pre-rounded fp16).
// PHASE==1: fused gate/up GEMM + SiLU-mul -> g_hh. CTA tile 128x(64|64)
//           (gate cols n0..n0+63 and up cols n0..n0+63), NB=2, BN=64,
//           STAGES=2, smem 64KB -> OCCUPANCY 2 (was 1).
// PHASE==2: down GEMM -> out. CTA tile 128x128, NB=1, STAGES=3, occ 2 (as R11).
// BK=64 fp16 (128B rows), 8 warps (2 x 4), XOR-swizzled smem, ldmatrix.
// ---------------------------------------------------------------------------
template <int PHASE>
__global__ void __launch_bounds__(256, 2) gemm_tc_kernel(
    const __half* __restrict__ W, const float* __restrict__ BL,
    float* __restrict__ outp) {
    constexpr int KD = (PHASE == 1) ? H_ : D_;
    constexpr int OUTS = (PHASE == 1) ? D_ : H_;
    constexpr int NB = (PHASE == 1) ? 2 : 1;
    constexpr int BN = (PHASE == 1) ? 64 : 128;     // cols per B block
    constexpr int STAGES = (PHASE == 1) ? 2 : 3;
    constexpr int KT = KD / 64;
    constexpr int WARPN = BN / 4;                   // cols per warp (16 / 32)
    constexpr int NI = WARPN / 8;                   // n8 frags per warp (2 / 4)
    constexpr int NLD = WARPN / 16;                 // B ldsm4 per block (1 / 2)
    constexpr uint32_t STAGE_BYTES = (128 + NB * BN) * 128;   // 32 KB both

    extern __shared__ float smem[];

    const __half* Ain = (PHASE == 1) ? g_xh : g_hh;
    const float* LOW = (PHASE == 1) ? g_low_gu : g_low_d;

    const int e = blockIdx.z;
    const int m0 = blockIdx.x * 128;
    const int n0 = blockIdx.y * BN;

    const int tid = threadIdx.x;
    const int lane = tid & 31;
    const int wid = tid >> 5;
    const int wm = wid & 1;
    const int wn = wid >> 1;

    const __half* Abase = Ain + ((size_t)e * T_ + m0) * KD;
    const __half* Wb0 = W + ((size_t)e * NB * OUTS + n0) * KD;          // gate / down
    const __half* Wb1 = W + ((size_t)e * NB * OUTS + OUTS + n0) * KD;   // up (NB==2)

    const uint32_t sbase = smem_u32(smem);

    auto load_stage = [&](int s, int k0) {
        const uint32_t st = sbase + (uint32_t)s * STAGE_BYTES;
#pragma unroll
        for (int i = 0; i < (128 + NB * BN) / 32; i++) {   // 8 cp.async / thread
            int gi = tid + i * 256;
            int row = gi >> 3;
            int gc = gi & 7;
            uint32_t soff = (uint32_t)(row * 128 + ((gc ^ (row & 7)) << 4));
            const __half* src;
            if (row < 128) src = Abase + (size_t)row * KD;
            else if (row < 128 + BN) src = Wb0 + (size_t)(row - 128) * KD;
            else src = Wb1 + (size_t)(row - 128 - BN) * KD;
            cp_async16(st + soff, src + k0 + gc * 8);
        }
    };

    float acc[NB][4][NI][4];
#pragma unroll
    for (int b = 0; b < NB; b++)
#pragma unroll
        for (int mi = 0; mi < 4; mi++)
#pragma unroll
            for (int ni = 0; ni < NI; ni++)
#pragma unroll
                for (int q = 0; q < 4; q++) acc[b][mi][ni][q] = 0.0f;

    auto compute_stage = [&](int s) {
        const uint32_t st = sbase + (uint32_t)s * STAGE_BYTES;
#pragma unroll
        for (int ks = 0; ks < 4; ks++) {     // 4 x k16 = BK 64
            uint32_t af[4][4];
#pragma unroll
            for (int mi = 0; mi < 4; mi++) {
                int row = wm * 64 + mi * 16 + (lane & 15);
                int gcs = (ks << 1) + (lane >> 4);
                uint32_t addr = st + (uint32_t)(row * 128 + ((gcs ^ (row & 7)) << 4));
                ldsm4(addr, af[mi][0], af[mi][1], af[mi][2], af[mi][3]);
            }
            uint32_t bf[NB][NI][2];
#pragma unroll
            for (int b = 0; b < NB; b++) {
                uint32_t bt = st + 16384u + (uint32_t)(b * BN * 128);
#pragma unroll
                for (int p = 0; p < NLD; p++) {
                    int row = wn * WARPN + p * 16 + ((lane >> 4) << 3) + (lane & 7);
                    int gcs = (ks << 1) + ((lane >> 3) & 1);
                    uint32_t addr = bt + (uint32_t)(row * 128 + ((gcs ^ (row & 7)) << 4));
                    ldsm4(addr, bf[b][2 * p][0], bf[b][2 * p][1],
                          bf[b][2 * p + 1][0], bf[b][2 * p + 1][1]);
                }
            }
#pragma unroll
            for (int b = 0; b < NB; b++)
#pragma unroll
                for (int mi = 0; mi < 4; mi++)
#pragma unroll
                    for (int ni = 0; ni < NI; ni++)
                        mma_f16(acc[b][mi][ni], af[mi], bf[b][ni]);
        }
    };

    // ---- pipeline ----
    if constexpr (STAGES == 2) {
        load_stage(0, 0); cp_commit();
        for (int kt = 0; kt < KT; kt++) {
            if (kt + 1 < KT) {
                load_stage((kt + 1) & 1, (kt + 1) * 64);
                cp_commit();
                cp_wait<1>();
            } else {
                cp_wait<0>();
            }
            __syncthreads();
            compute_stage(kt & 1);
            __syncthreads();   // protect buffer reuse by next load
        }
    } else {
        load_stage(0, 0); cp_commit();
        load_stage(1, 64); cp_commit();
        for (int kt = 0; kt < KT; kt++) {
            cp_wait<1>();
            __syncthreads();
            int lk = kt + 2;
            if (lk < KT) load_stage(lk % 3, lk * 64);
            cp_commit();
            compute_stage(kt % 3);
        }
        cp_wait<0>();
        __syncthreads();
    }

    // ---- epilogue: stage low-rank tiles in smem (reuse stage 0) ----
    float* s_low = smem;          // [128][8]
    float* s_bl = smem + 1024;    // [NB*BN][8] contiguous (block0 then block1)
    {
        int r_ = tid >> 1;
        int h4 = (tid & 1) * 4;
        ((float4*)s_low)[tid] = *(const float4*)(LOW + ((size_t)e * T_ + m0 + r_) * R_ + h4);
        const float* bl0 = BL + ((size_t)e * NB * OUTS + n0) * R_;
        const float* bl1 = BL + ((size_t)e * NB * OUTS + OUTS + n0) * R_;
        // NB*BN*8 floats = 1024 -> 256 float4, one per thread
        int br = tid >> 1;                 // global block-row 0..127
        const float* src = (br < BN) ? (bl0 + (size_t)br * R_ + h4)
                                     : (bl1 + (size_t)(br - BN) * R_ + h4);
        ((float4*)s_bl)[tid] = *(const float4*)src;
    }
    __syncthreads();

    const int g = lane >> 2;
    const int tg = lane & 3;
#pragma unroll
    for (int mi = 0; mi < 4; mi++) {
#pragma unroll
        for (int rs = 0; rs < 2; rs++) {
            int lr = wm * 64 + mi * 16 + g + rs * 8;
            float lw[8];
#pragma unroll
            for (int r = 0; r < 8; r++) lw[r] = s_low[lr * 8 + r];
#pragma unroll
            for (int ni = 0; ni < NI; ni++) {
                int lc = wn * WARPN + ni * 8 + tg * 2;
                float v[2];
#pragma unroll
                for (int cc = 0; cc < 2; cc++) {
                    int col = lc + cc;
                    float dg = 0.0f;
#pragma unroll
                    for (int r = 0; r < 8; r++) dg += lw[r] * s_bl[col * 8 + r];
                    float gv = acc[0][mi][ni][rs * 2 + cc] + SCALE_ * dg;
                    if constexpr (NB == 2) {
                        float du = 0.0f;
#pragma unroll
                        for (int r = 0; r < 8; r++) du += lw[r] * s_bl[(BN + col) * 8 + r];
                        float uv = acc[1][mi][ni][rs * 2 + cc] + SCALE_ * du;
                        v[cc] = uv * gv / (1.0f + __expf(-gv));   // h = up*silu(gate)
                    } else {
                        v[cc] = gv;
                    }
                }
                if constexpr (PHASE == 1) {
                    __half* orow = g_hh + ((size_t)e * T_ + m0 + lr) * OUTS + n0;
                    *(__half2*)(orow + lc) = __floats2half2_rn(v[0], v[1]);
                } else {
                    float* orow = outp + ((size_t)e * T_ + m0 + lr) * OUTS + n0;
                    *(float2*)(orow + lc) = make_float2(v[0], v[1]);
                }
            }
        }
    }
}

// ---------------------------------------------------------------------------
// Launch
// ---------------------------------------------------------------------------
extern "C" void kernel_launch(void* const* d_in, const int* in_sizes, int n_in,
                              void* d_out, int out_size) {
    (void)in_sizes; (void)n_in; (void)out_size;
    const float* x    = (const float*)d_in[0];
    const float* W_gu = (const float*)d_in[1];
    const float* A_gu = (const float*)d_in[2];
    const float* B_gu = (const float*)d_in[3];
    const float* W_d  = (const float*)d_in[4];
    const float* A_d  = (const float*)d_in[5];
    const float* B_d  = (const float*)d_in[6];
    float* out = (float*)d_out;

    static __half* p_xh = nullptr;
    static __half* p_wguh = nullptr;
    static __half* p_wdh = nullptr;
    if (!p_xh) {  // symbol address lookups (not allocations); idempotent
        cudaGetSymbolAddress((void**)&p_xh, g_xh);
        cudaGetSymbolAddress((void**)&p_wguh, g_wguh);
        cudaGetSymbolAddress((void**)&p_wdh, g_wdh);
        const int smem1 = 2 * 32768;  //  65536 B -> occupancy 2
        const int smem2 = 3 * 32768;  //  98304 B -> occupancy 2
        cudaFuncSetAttribute(gemm_tc_kernel<1>,
                             cudaFuncAttributeMaxDynamicSharedMemorySize, smem1);
        cudaFuncSetAttribute(gemm_tc_kernel<2>,
                             cudaFuncAttributeMaxDynamicSharedMemorySize, smem2);
    }

    // 0) pre-round operands to fp16 (RNE)
    round_half_kernel<<<2048, 256>>>((const float4*)x, (uint4*)p_xh,
                                     E_ * T_ * H_ / 8);
    round_half_kernel<<<8192, 256>>>((const float4*)W_gu, (uint4*)p_wguh,
                                     E_ * 2 * D_ * (H_ / 8));
    round_half_kernel<<<8192, 256>>>((const float4*)W_d, (uint4*)p_wdh,
                                     E_ * H_ * (D_ / 8));

    // 1) low_gu = x @ A_gu^T (fp16 x, fp32 A/accum)
    lora_low_kernel<0><<<dim3(T_ / 8, E_), 256>>>(A_gu);
    // 2) h = up * silu(gate): fused gate/up GEMM + LoRA + GLU epilogue -> g_hh
    gemm_tc_kernel<1><<<dim3(T_ / 128, D_ / 64, E_), 256, 2 * 32768>>>(
        p_wguh, B_gu, nullptr);
    // 3) low_d = h @ A_d^T
    lora_low_kernel<1><<<dim3(T_ / 8, E_), 256>>>(A_d);
    // 4) out = h @ W_d^T + SCALE * low_d @ B_d^T
    gemm_tc_kernel<2><<<dim3(T_ / 128, H_ / 128, E_), 256, 3 * 32768>>>(
        p_wdh, B_d, out);
}